// round 4
// baseline (speedup 1.0000x reference)
#include <cuda_runtime.h>
#include <math.h>

#define NB   512
#define CIN  156
#define COUT 50
#define TT   325
#define THREADS 320

#define CCHUNK 12
#define NCHUNK 13
#define NPAIR  6
#define XROW2F 852          // floats per interleaved pair-row: 2*(100 pad + 325) + 2
#define PAD2   100

#define CONV_NTG  41
#define CONV_TILE 8
#define CONV_ACT  (NPAIR*CONV_NTG)   // 246

#define GEMM_ACT  300       // 25 pairs x 12 t-groups
#define GEMM_TILE 28

#define PSP_STR 328
#define Y_STR   672         // floats per output-pair row (336 t-slots x 2ch)

// smem float offsets
#define OFF_EPS  0                              // 200
#define OFF_XI2  200
#define XI2_SZ   (NPAIR*XROW2F + 24)            // 5136
#define OFF_PSPC (OFF_XI2 + XI2_SZ)             // 5336
#define OFF_WS   (OFF_PSPC + CCHUNK*PSP_STR)    // 9272
#define OFF_Y    (OFF_WS + CCHUNK*52)           // 9896
#define SMEM_FLOATS (OFF_Y + 25*Y_STR)          // 26696 floats = 106,784 B

typedef unsigned long long ull;

__device__ __forceinline__ ull pack2(float lo, float hi) {
    ull r; asm("mov.b64 %0, {%1, %2};" : "=l"(r) : "f"(lo), "f"(hi)); return r;
}
__device__ __forceinline__ void unpack2(ull v, float &lo, float &hi) {
    asm("mov.b64 {%0, %1}, %2;" : "=f"(lo), "=f"(hi) : "l"(v));
}
__device__ __forceinline__ void fma2(ull &d, ull a, ull b) {
    asm("fma.rn.f32x2 %0, %1, %2, %0;" : "+l"(d) : "l"(a), "l"(b));
}

__global__ __launch_bounds__(THREADS, 2)
void enc_kernel(const float* __restrict__ x, const float* __restrict__ w,
                float* __restrict__ out)
{
    extern __shared__ float sm[];
    const int b = blockIdx.x;
    const int tid = threadIdx.x;

    // ---- P0: eps taps (jnp op sequence), pads, zero y accumulators ----
    if (tid < 100) {
        float tk = (float)tid / 10.0f;
        float e  = tk * expf(1.0f - tk);
        ((ull*)(sm + OFF_EPS))[tid] = pack2(e, e);
    }
    for (int i = tid; i < NPAIR * PAD2 * 2; i += THREADS) {
        int pr = i / (PAD2 * 2), off = i % (PAD2 * 2);
        sm[OFF_XI2 + pr * XROW2F + off] = 0.0f;
    }
    for (int i = tid; i < 24; i += THREADS) sm[OFF_XI2 + NPAIR * XROW2F + i] = 0.0f;
    for (int i = tid; i < CCHUNK * 3; i += THREADS)   // pspC tail t=325..327 stays 0
        sm[OFF_PSPC + (i / 3) * PSP_STR + 325 + (i % 3)] = 0.0f;
    for (int i = tid; i < 25 * Y_STR; i += THREADS) sm[OFF_Y + i] = 0.0f;

    // conv thread mapping
    const int cpr = tid / CONV_NTG;            // 0..5
    const int ctg = tid % CONV_NTG;            // 0..40
    const int ct0 = ctg * CONV_TILE;           // even
    const bool cact = (tid < CONV_ACT);
    const ull* e2 = (const ull*)(sm + OFF_EPS);

    // gemm thread mapping: pair-per-thread
    const int gm  = tid % 25;                  // output pair
    const int gtg = tid / 25;                  // 0..11
    const int gt0 = gtg * GEMM_TILE;
    const bool gact = (tid < GEMM_ACT);

    for (int cc = 0; cc < NCHUNK; cc++) {
        __syncthreads();   // prev chunk's GEMM done: XI2/pspC/WS reusable
        {   // load x chunk (pair-interleaved) + W chunk (transposed)
            const float* xb = x + ((size_t)b * CIN + cc * CCHUNK) * TT;
            for (int i = tid; i < CCHUNK * TT; i += THREADS) {
                int cl = i / TT, t = i % TT;
                sm[OFF_XI2 + (cl >> 1) * XROW2F + 2 * (PAD2 + t) + (cl & 1)] = xb[i];
            }
            for (int i = tid; i < CCHUNK * COUT; i += THREADS) {
                int cl = i / COUT, o = i % COUT;
                sm[OFF_WS + cl * 52 + o] = w[o * CIN + cc * CCHUNK + cl];
            }
        }
        __syncthreads();

        // ---- conv: 100-tap FIR, ascending k, channel-pair f32x2 ----
        if (cact) {
            ull acc2[CONV_TILE];
            #pragma unroll
            for (int j = 0; j < CONV_TILE; j++) acc2[j] = 0ULL;

            const float* rowf = sm + OFF_XI2 + cpr * XROW2F;
            ull W[12];
            {   // init window: float2 idx [96+ct0 .. 96+ct0+11]
                const ulonglong2* p = (const ulonglong2*)(rowf + 2 * (96 + ct0));
                #pragma unroll
                for (int m = 0; m < 6; m++) { ulonglong2 v = p[m]; W[2*m] = v.x; W[2*m+1] = v.y; }
            }
            #pragma unroll
            for (int kk = 0; kk < 100; kk += 4) {
                #pragma unroll
                for (int i = 0; i < 4; i++) {
                    ull ek = e2[kk + i];
                    #pragma unroll
                    for (int j = 0; j < CONV_TILE; j++)
                        fma2(acc2[j], ek, W[j - i + 4]);
                }
                if (kk < 96) {
                    #pragma unroll
                    for (int m = 11; m >= 4; m--) W[m] = W[m - 4];
                    const ulonglong2* p = (const ulonglong2*)(rowf + 2 * (92 + ct0 - kk));
                    ulonglong2 v0 = p[0], v1 = p[1];
                    W[0] = v0.x; W[1] = v0.y; W[2] = v1.x; W[3] = v1.y;
                }
            }
            // store chunk psp (stride 328; t>=325 slots untouched zeros)
            #pragma unroll
            for (int j = 0; j < CONV_TILE; j++) {
                int t = ct0 + j;
                if (t < TT) {
                    float lo, hi; unpack2(acc2[j], lo, hi);
                    sm[OFF_PSPC + (2 * cpr)     * PSP_STR + t] = lo;
                    sm[OFF_PSPC + (2 * cpr + 1) * PSP_STR + t] = hi;
                }
            }
        }
        __syncthreads();

        // ---- GEMM accumulate: y[pair][t] += sum_cl w*psp, ascending c ----
        if (gact) {
            ulonglong2* yp = (ulonglong2*)(sm + OFF_Y + gm * Y_STR + 2 * gt0);
            ull acc[GEMM_TILE];
            #pragma unroll
            for (int q = 0; q < GEMM_TILE / 2; q++) {
                ulonglong2 v = yp[q]; acc[2*q] = v.x; acc[2*q+1] = v.y;
            }
            #pragma unroll 2
            for (int cl = 0; cl < CCHUNK; cl++) {
                const float* xrow = sm + OFF_PSPC + cl * PSP_STR + gt0;
                ull wv = *(const ull*)(sm + OFF_WS + cl * 52 + 2 * gm);
                #pragma unroll
                for (int q = 0; q < GEMM_TILE / 4; q++) {
                    float4 f = *(const float4*)(xrow + 4 * q);
                    fma2(acc[4*q+0], wv, pack2(f.x, f.x));
                    fma2(acc[4*q+1], wv, pack2(f.y, f.y));
                    fma2(acc[4*q+2], wv, pack2(f.z, f.z));
                    fma2(acc[4*q+3], wv, pack2(f.w, f.w));
                }
            }
            #pragma unroll
            for (int q = 0; q < GEMM_TILE / 2; q++) {
                ulonglong2 v; v.x = acc[2*q]; v.y = acc[2*q+1]; yp[q] = v;
            }
        }
    }
    __syncthreads();

    // ---- scan: exact refractory recursion (bit-replicates jax), in-place ----
    if (tid < COUT) {
        const int o = tid;
        float* ybase = sm + OFF_Y + (o >> 1) * Y_STR + (o & 1);

        float nu1[31];
        #pragma unroll
        for (int d = 1; d <= 31; d++) {
            float td = (float)d;
            nu1[d - 1] = (-20.0f * td) * expf(1.0f - td);
        }
        float rf[32];
        #pragma unroll
        for (int i = 0; i < 32; i++) rf[i] = 0.0f;

        for (int t = 0; t < TT; t++) {
            float v = ybase[2 * t] + rf[0];
            float s = (v >= 10.0f) ? 1.0f : 0.0f;
            ybase[2 * t] = s;
            #pragma unroll
            for (int i = 0; i < 31; i++) rf[i] = fmaf(s, nu1[i], rf[i + 1]);
            rf[31] = 0.0f;
        }
    }
    __syncthreads();

    // ---- copy-out ----
    float* ob = out + (size_t)b * (COUT * TT);
    for (int i = tid; i < COUT * TT; i += THREADS) {
        int o = i / TT, t = i % TT;
        ob[i] = sm[OFF_Y + (o >> 1) * Y_STR + 2 * t + (o & 1)];
    }
}

extern "C" void kernel_launch(void* const* d_in, const int* in_sizes, int n_in,
                              void* d_out, int out_size)
{
    const float* x = (const float*)d_in[0];
    const float* w = (const float*)d_in[1];
    if (n_in >= 2 && in_sizes[0] == COUT * CIN) {
        x = (const float*)d_in[1];
        w = (const float*)d_in[0];
    }
    cudaFuncSetAttribute(enc_kernel, cudaFuncAttributeMaxDynamicSharedMemorySize,
                         SMEM_FLOATS * (int)sizeof(float));
    enc_kernel<<<NB, THREADS, SMEM_FLOATS * sizeof(float)>>>(x, w, (float*)d_out);
}

// round 5
// speedup vs baseline: 1.5326x; 1.5326x over previous
#include <cuda_runtime.h>
#include <math.h>

#define NB   512
#define CIN  156
#define COUT 50
#define TT   325
#define THREADS 512

#define CCHUNK 26
#define NCHUNK 6
#define NPAIR  13

#define CONV_NTG  33
#define CONV_TILE 10
#define CONV_ACT  (NPAIR*CONV_NTG)   // 429

#define OG 5
#define GEMM_TILE 4
#define GEMM_NTG  82
#define GEMM_ACT  (OG*GEMM_NTG)      // 410

#define XROWF   432                  // 100 pad + 325 + 7 slack
#define XI2BUF  (CCHUNK*XROWF)       // 11232
#define PSP_STR 332
#define YST_STR 332

// smem float offsets
#define OFF_EPS 0                      // ull eps2[100] = 200 floats
#define OFF_W   200                    // Ws[156][52] transposed = 8112
#define OFF_XI2 8312                   // 2 x chunk buffers
#define OFF_PSP (OFF_XI2 + 2*XI2BUF)   // 30776; pspC[26][332]
#define SMEM_FLOATS (OFF_PSP + CCHUNK*PSP_STR)  // 39408 fl = 157,632 B
#define OFF_YST OFF_XI2                // y staging reuses XI2 (needs 16600 fl)

typedef unsigned long long ull;

__device__ float g_y[(size_t)NB * COUT * TT];   // 33.3 MB scratch

__device__ __forceinline__ ull pack2(float lo, float hi) {
    ull r; asm("mov.b64 %0, {%1, %2};" : "=l"(r) : "f"(lo), "f"(hi)); return r;
}
__device__ __forceinline__ void unpack2(ull v, float &lo, float &hi) {
    asm("mov.b64 {%0, %1}, %2;" : "=f"(lo), "=f"(hi) : "l"(v));
}
__device__ __forceinline__ void fma2(ull &d, ull a, ull b) {
    asm("fma.rn.f32x2 %0, %1, %2, %0;" : "+l"(d) : "l"(a), "l"(b));
}
__device__ __forceinline__ unsigned smem_u32(const void* p) {
    return (unsigned)__cvta_generic_to_shared(p);
}
__device__ __forceinline__ void cpa4(unsigned dst, const float* src) {
    asm volatile("cp.async.ca.shared.global [%0], [%1], 4;" :: "r"(dst), "l"(src));
}
__device__ __forceinline__ void cpa_commit() {
    asm volatile("cp.async.commit_group;");
}

__global__ __launch_bounds__(THREADS, 1)
void convgemm_kernel(const float* __restrict__ x, const float* __restrict__ w)
{
    extern __shared__ float sm[];
    const int b = blockIdx.x;
    const int tid = threadIdx.x;

    // ---- eps taps (jnp op sequence) + zero pads of both x buffers ----
    if (tid < 100) {
        float tk = (float)tid / 10.0f;
        float e  = tk * expf(1.0f - tk);
        ((ull*)(sm + OFF_EPS))[tid] = pack2(e, e);
    }
    for (int i = tid; i < 2 * CCHUNK * 100; i += THREADS) {
        int buf = i / (CCHUNK * 100);
        int rem = i - buf * (CCHUNK * 100);
        int row = rem / 100, off = rem - row * 100;
        sm[OFF_XI2 + buf * XI2BUF + row * XROWF + off] = 0.0f;
    }

    // ---- prologue: async-load all W (transposed) + x chunk 0 ----
    {
        for (int i = tid; i < CIN * COUT; i += THREADS) {
            int c = i / COUT, o = i - c * COUT;
            cpa4(smem_u32(sm + OFF_W + c * 52 + o), w + o * CIN + c);
        }
        const float* xb = x + (size_t)b * (CIN * TT);
        for (int i = tid; i < CCHUNK * TT; i += THREADS) {
            int cl = i / TT, t = i - cl * TT;
            cpa4(smem_u32(sm + OFF_XI2 + cl * XROWF + 100 + t), xb + cl * TT + t);
        }
        cpa_commit();
    }

    // thread mappings
    const int cpr = tid / CONV_NTG;            // 0..12
    const int ctg = tid % CONV_NTG;            // 0..32
    const int ct0 = ctg * CONV_TILE;           // even
    const bool cact = (tid < CONV_ACT);
    const ull* e2 = (const ull*)(sm + OFF_EPS);

    const int og  = tid % OG;                  // 0..4
    const int gtg = tid / OG;                  // 0..102
    const int gt0 = gtg * GEMM_TILE;
    const int obase = og * 10;
    const bool gact = (tid < GEMM_ACT);

    ull acc[OG][GEMM_TILE];                    // persistent y accumulators
    #pragma unroll
    for (int m = 0; m < OG; m++)
        #pragma unroll
        for (int j = 0; j < GEMM_TILE; j++) acc[m][j] = 0ULL;

    for (int cc = 0; cc < NCHUNK; cc++) {
        // prefetch next chunk
        if (cc + 1 < NCHUNK) {
            const float* xb = x + ((size_t)b * CIN + (cc + 1) * CCHUNK) * TT;
            float* dstb = sm + OFF_XI2 + ((cc + 1) & 1) * XI2BUF;
            for (int i = tid; i < CCHUNK * TT; i += THREADS) {
                int cl = i / TT, t = i - cl * TT;
                cpa4(smem_u32(dstb + cl * XROWF + 100 + t), xb + cl * TT + t);
            }
            cpa_commit();
            asm volatile("cp.async.wait_group 1;");
        } else {
            asm volatile("cp.async.wait_group 0;");
        }
        __syncthreads();    // chunk cc data visible; prev GEMM done (pspC reusable)

        // ---- conv: 100-tap FIR, ascending k, channel-pair f32x2 ----
        if (cact) {
            const float* rowA = sm + OFF_XI2 + (cc & 1) * XI2BUF + (2 * cpr) * XROWF;
            const float* rowB = rowA + XROWF;

            ull acc2[CONV_TILE];
            #pragma unroll
            for (int j = 0; j < CONV_TILE; j++) acc2[j] = 0ULL;

            ull W[14];
            #pragma unroll
            for (int m = 0; m < 7; m++) {       // init window: idx 96+ct0 .. +13
                float2 va = *(const float2*)(rowA + 96 + ct0 + 2 * m);
                float2 vb = *(const float2*)(rowB + 96 + ct0 + 2 * m);
                W[2 * m]     = pack2(va.x, vb.x);
                W[2 * m + 1] = pack2(va.y, vb.y);
            }
            #pragma unroll
            for (int kk = 0; kk < 100; kk += 4) {
                #pragma unroll
                for (int i = 0; i < 4; i++) {
                    ull ek = e2[kk + i];
                    #pragma unroll
                    for (int j = 0; j < CONV_TILE; j++)
                        fma2(acc2[j], ek, W[j - i + 4]);
                }
                if (kk < 96) {
                    #pragma unroll
                    for (int m = 13; m >= 4; m--) W[m] = W[m - 4];
                    float2 a0 = *(const float2*)(rowA + 92 + ct0 - kk);
                    float2 a1 = *(const float2*)(rowA + 94 + ct0 - kk);
                    float2 b0 = *(const float2*)(rowB + 92 + ct0 - kk);
                    float2 b1 = *(const float2*)(rowB + 94 + ct0 - kk);
                    W[0] = pack2(a0.x, b0.x); W[1] = pack2(a0.y, b0.y);
                    W[2] = pack2(a1.x, b1.x); W[3] = pack2(a1.y, b1.y);
                }
            }
            #pragma unroll
            for (int j = 0; j < CONV_TILE; j++) {
                int t = ct0 + j;
                if (t < TT) {
                    float lo, hi; unpack2(acc2[j], lo, hi);
                    sm[OFF_PSP + (2 * cpr)     * PSP_STR + t] = lo;
                    sm[OFF_PSP + (2 * cpr + 1) * PSP_STR + t] = hi;
                }
            }
        }
        __syncthreads();

        // ---- GEMM accumulate: ascending c ----
        if (gact) {
            const float* wsc = sm + OFF_W + (cc * CCHUNK) * 52 + obase;
            #pragma unroll 2
            for (int cl = 0; cl < CCHUNK; cl++) {
                float4 f = *(const float4*)(sm + OFF_PSP + cl * PSP_STR + gt0);
                ull xp[4];
                xp[0] = pack2(f.x, f.x); xp[1] = pack2(f.y, f.y);
                xp[2] = pack2(f.z, f.z); xp[3] = pack2(f.w, f.w);
                const ull* wrow = (const ull*)(wsc + cl * 52);
                ull wv[5];
                #pragma unroll
                for (int m = 0; m < 5; m++) wv[m] = wrow[m];
                #pragma unroll
                for (int m = 0; m < 5; m++)
                    #pragma unroll
                    for (int j = 0; j < GEMM_TILE; j++)
                        fma2(acc[m][j], wv[m], xp[j]);
            }
        }
    }

    // ---- stage y in smem, then coalesced store to scratch ----
    __syncthreads();
    if (gact) {
        #pragma unroll
        for (int m = 0; m < 5; m++)
            #pragma unroll
            for (int j = 0; j < GEMM_TILE; j++) {
                int t = gt0 + j;
                if (t < TT) {
                    float lo, hi; unpack2(acc[m][j], lo, hi);
                    sm[OFF_YST + (obase + 2 * m)     * YST_STR + t] = lo;
                    sm[OFF_YST + (obase + 2 * m + 1) * YST_STR + t] = hi;
                }
            }
    }
    __syncthreads();
    float* yb = g_y + (size_t)b * (COUT * TT);
    for (int i = tid; i < COUT * TT; i += THREADS) {
        int o = i / TT, t = i - o * TT;
        yb[i] = sm[OFF_YST + o * YST_STR + t];
    }
}

__global__ __launch_bounds__(128, 8)
void scan_kernel(float* __restrict__ out)
{
    const int r = blockIdx.x * 128 + threadIdx.x;   // (b,o) row, 0..25599
    if (r >= NB * COUT) return;
    const float* yrow = g_y + (size_t)r * TT;
    float* orow = out + (size_t)r * TT;

    float nu1[31];
    #pragma unroll
    for (int d = 1; d <= 31; d++) {
        float td = (float)d;
        nu1[d - 1] = (-20.0f * td) * expf(1.0f - td);
    }
    float rf[32];
    #pragma unroll
    for (int i = 0; i < 32; i++) rf[i] = 0.0f;

    #pragma unroll 5
    for (int t = 0; t < TT; t++) {
        float v = yrow[t] + rf[0];
        float s = (v >= 10.0f) ? 1.0f : 0.0f;
        orow[t] = s;
        #pragma unroll
        for (int i = 0; i < 31; i++) rf[i] = fmaf(s, nu1[i], rf[i + 1]);
        rf[31] = 0.0f;
    }
}

extern "C" void kernel_launch(void* const* d_in, const int* in_sizes, int n_in,
                              void* d_out, int out_size)
{
    const float* x = (const float*)d_in[0];
    const float* w = (const float*)d_in[1];
    if (n_in >= 2 && in_sizes[0] == COUT * CIN) {
        x = (const float*)d_in[1];
        w = (const float*)d_in[0];
    }
    cudaFuncSetAttribute(convgemm_kernel, cudaFuncAttributeMaxDynamicSharedMemorySize,
                         SMEM_FLOATS * (int)sizeof(float));
    convgemm_kernel<<<NB, THREADS, SMEM_FLOATS * sizeof(float)>>>(x, w);
    scan_kernel<<<(NB * COUT + 127) / 128, 128>>>((float*)d_out);
}

// round 6
// speedup vs baseline: 1.9183x; 1.2517x over previous
#include <cuda_runtime.h>
#include <math.h>

#define NB   512
#define CIN  156
#define COUT 50
#define TT   325
#define THREADS 256

#define CCH   26
#define NCH   6
#define NPAIR 13

// conv: 13 pairs x 17 t-groups, tile 10 (even -> aligned LDS.128, 80B lane stride = conflict-free)
#define CNTG  17
#define CTILE 10
#define CACT  221

// gemm role-swap: 10 o-groups (5 o each) x 21 t-groups (4 ulls = 8 t each)
#define GOG   10
#define GNTG  21
#define GACT  210

#define XROW2F 544                 // floats per interleaved pair row (272 ulls)
#define XI2BUF (NPAIR*XROW2F)      // 7072 floats
#define PSTR   168

// smem float offsets (per CTA, 85,248 B -> 2 CTAs/SM)
#define OFF_EPS 0                  // 200
#define OFF_WD  200                // Wd[26][50] dup ulls = 2600 fl
#define OFF_PSP 2800               // pspC[26][168] = 4368 fl
#define OFF_XI2 7168               // 2 x 7072 fl
#define SMEM_FLOATS 21312
#define OFF_YST OFF_XI2            // y staging [168][52] t-major = 8736 fl (reuses XI2)

#define SROWS (NB*COUT)            // 25600

typedef unsigned long long ull;

__device__ float g_y[(size_t)TT * SROWS];   // t-major scratch, 33.3 MB

__device__ __forceinline__ ull pack2(float lo, float hi) {
    ull r; asm("mov.b64 %0, {%1, %2};" : "=l"(r) : "f"(lo), "f"(hi)); return r;
}
__device__ __forceinline__ void unpack2(ull v, float &lo, float &hi) {
    asm("mov.b64 {%0, %1}, %2;" : "=f"(lo), "=f"(hi) : "l"(v));
}
__device__ __forceinline__ void fma2(ull &d, ull a, ull b) {
    asm("fma.rn.f32x2 %0, %1, %2, %0;" : "+l"(d) : "l"(a), "l"(b));
}
__device__ __forceinline__ unsigned smem_u32(const void* p) {
    return (unsigned)__cvta_generic_to_shared(p);
}
__device__ __forceinline__ void cpa4(unsigned dst, const float* src) {
    asm volatile("cp.async.ca.shared.global [%0], [%1], 4;" :: "r"(dst), "l"(src));
}
__device__ __forceinline__ void cpa_commit() { asm volatile("cp.async.commit_group;"); }

__global__ __launch_bounds__(THREADS, 2)
void convgemm_kernel(const float* __restrict__ x, const float* __restrict__ w)
{
    extern __shared__ float sm[];
    const int tid = threadIdx.x;
    const int b   = blockIdx.x >> 1;
    const int h   = blockIdx.x & 1;
    const int len = 163 - h;               // 163 / 162
    const int t0h = h * 163;
    const int pstart = h ? 0 : 100;
    const int cnt = 100 + len - pstart;    // floats loaded per channel per chunk

    // ---- eps taps (jnp op sequence) ----
    if (tid < 100) {
        float tk = (float)tid / 10.0f;
        float e  = tk * expf(1.0f - tk);
        ((ull*)(sm + OFF_EPS))[tid] = pack2(e, e);
    }
    // zero pad p<100 of both x buffers (needed for h==0; harmless else)
    for (int i = tid; i < NPAIR * 200 * 2; i += THREADS) {
        int buf = i / (NPAIR * 200), rem = i % (NPAIR * 200);
        sm[OFF_XI2 + buf * XI2BUF + (rem / 200) * XROW2F + (rem % 200)] = 0.0f;
    }
    // zero psp pad t in [len,168)
    for (int i = tid; i < CCH * (PSTR - len); i += THREADS) {
        int row = i / (PSTR - len), off = i % (PSTR - len);
        sm[OFF_PSP + row * PSTR + len + off] = 0.0f;
    }

    // ---- prologue: x chunk 0 (cp.async) + w chunk 0 (regs) ----
    {
        const float* xb = x + ((size_t)b * CIN) * TT + (t0h - 100);
        for (int i = tid; i < CCH * cnt; i += THREADS) {
            int cl = i / cnt, p = pstart + i % cnt;
            cpa4(smem_u32(sm + OFF_XI2 + (cl >> 1) * XROW2F + 2 * p + (cl & 1)),
                 xb + cl * TT + p);
        }
        cpa_commit();
    }
    float wR[6];
    {
        int j = 0;
        for (int i = tid; i < CCH * COUT; i += THREADS, j++) {
            int o = i / CCH, cl = i % CCH;
            wR[j] = w[o * CIN + cl];
        }
    }

    // thread mappings
    const int cpr = tid / CNTG, ctg = tid % CNTG;
    const int ct0 = ctg * CTILE;
    const bool cact = (tid < CACT);
    const ull* e2 = (const ull*)(sm + OFF_EPS);

    const int og = tid / GNTG, gtg = tid % GNTG;
    const int gt0fl = gtg * 8;
    const bool gact = (tid < GACT);

    ull acc[5][4];
    #pragma unroll
    for (int m = 0; m < 5; m++)
        #pragma unroll
        for (int q = 0; q < 4; q++) acc[m][q] = 0ULL;

    for (int cc = 0; cc < NCH; cc++) {
        if (cc + 1 < NCH) {
            const float* xb = x + ((size_t)b * CIN + (cc + 1) * CCH) * TT + (t0h - 100);
            float* dstb = sm + OFF_XI2 + ((cc + 1) & 1) * XI2BUF;
            for (int i = tid; i < CCH * cnt; i += THREADS) {
                int cl = i / cnt, p = pstart + i % cnt;
                cpa4(smem_u32(dstb + (cl >> 1) * XROW2F + 2 * p + (cl & 1)),
                     xb + cl * TT + p);
            }
            cpa_commit();
            asm volatile("cp.async.wait_group 1;");
        } else {
            asm volatile("cp.async.wait_group 0;");
        }
        __syncthreads();    // chunk cc x data visible; prev GEMM done

        // duplicate-store Wd for chunk cc, then prefetch w for cc+1
        {
            int j = 0;
            for (int i = tid; i < CCH * COUT; i += THREADS, j++) {
                int o = i / CCH, cl = i % CCH;
                sm[OFF_WD + (cl * COUT + o) * 2]     = wR[j];
                sm[OFF_WD + (cl * COUT + o) * 2 + 1] = wR[j];
            }
            if (cc + 1 < NCH) {
                j = 0;
                for (int i = tid; i < CCH * COUT; i += THREADS, j++) {
                    int o = i / CCH, cl = i % CCH;
                    wR[j] = w[o * CIN + (cc + 1) * CCH + cl];
                }
            }
        }

        // ---- conv: 100-tap FIR, ascending k, interleaved channel pairs ----
        if (cact) {
            const float* rowf = sm + OFF_XI2 + (cc & 1) * XI2BUF + cpr * XROW2F;
            ull acc2[CTILE];
            #pragma unroll
            for (int j = 0; j < CTILE; j++) acc2[j] = 0ULL;

            ull W[14];
            {
                const ulonglong2* p = (const ulonglong2*)(rowf + 2 * (96 + ct0));
                #pragma unroll
                for (int m = 0; m < 7; m++) { ulonglong2 v = p[m]; W[2*m] = v.x; W[2*m+1] = v.y; }
            }
            #pragma unroll
            for (int kk = 0; kk < 100; kk += 4) {
                #pragma unroll
                for (int i = 0; i < 4; i++) {
                    ull ek = e2[kk + i];
                    #pragma unroll
                    for (int j = 0; j < CTILE; j++)
                        fma2(acc2[j], ek, W[j - i + 4]);
                }
                if (kk < 96) {
                    #pragma unroll
                    for (int m = 13; m >= 4; m--) W[m] = W[m - 4];
                    const ulonglong2* p = (const ulonglong2*)(rowf + 2 * (92 + ct0 - kk));
                    ulonglong2 v0 = p[0], v1 = p[1];
                    W[0] = v0.x; W[1] = v0.y; W[2] = v1.x; W[3] = v1.y;
                }
            }
            #pragma unroll
            for (int j = 0; j < CTILE; j++) {
                int t = ct0 + j;
                if (t < len) {
                    float lo, hi; unpack2(acc2[j], lo, hi);
                    sm[OFF_PSP + (2 * cpr)     * PSTR + t] = lo;
                    sm[OFF_PSP + (2 * cpr + 1) * PSTR + t] = hi;
                }
            }
        }
        __syncthreads();    // psp + Wd visible

        // ---- GEMM: acc[o][t-pair] += wdup * x2 (natural pairs), ascending c ----
        if (gact) {
            #pragma unroll 2
            for (int cl = 0; cl < CCH; cl++) {
                const ulonglong2* xp = (const ulonglong2*)(sm + OFF_PSP + cl * PSTR + gt0fl);
                ulonglong2 x01 = xp[0], x23 = xp[1];
                const ull* wd = (const ull*)(sm + OFF_WD) + cl * COUT + og * 5;
                ull wv[5];
                #pragma unroll
                for (int m = 0; m < 5; m++) wv[m] = wd[m];
                #pragma unroll
                for (int m = 0; m < 5; m++) {
                    fma2(acc[m][0], wv[m], x01.x);
                    fma2(acc[m][1], wv[m], x01.y);
                    fma2(acc[m][2], wv[m], x23.x);
                    fma2(acc[m][3], wv[m], x23.y);
                }
            }
        }
    }

    // ---- stage y t-major in smem (XI2 now dead), then coalesced global store ----
    __syncthreads();
    if (gact) {
        #pragma unroll
        for (int m = 0; m < 5; m++) {
            int o = og * 5 + m;
            #pragma unroll
            for (int q = 0; q < 4; q++) {
                int t = 2 * (gtg * 4 + q);
                float lo, hi; unpack2(acc[m][q], lo, hi);
                sm[OFF_YST + t * 52 + o]       = lo;
                sm[OFF_YST + (t + 1) * 52 + o] = hi;
            }
        }
    }
    __syncthreads();
    {
        float* yb = g_y + (size_t)t0h * SROWS + b * COUT;
        for (int i = tid; i < len * COUT; i += THREADS) {
            int t = i / COUT, o = i % COUT;
            yb[(size_t)t * SROWS + o] = sm[OFF_YST + t * 52 + o];
        }
    }
}

// ---- scan: coalesced t-major reads, bit-exact refractory recursion ----
#define SC_SMEM ((2*32*256 + 256*33) * 4)    // 99,328 B

__global__ __launch_bounds__(256, 2)
void scan_kernel(float* __restrict__ out)
{
    extern __shared__ float ss[];
    float* sbuf = ss + 2 * 32 * 256;
    const int tid = threadIdx.x;
    const int r0 = blockIdx.x * 256;

    {   // prefetch tile 0
        const float* src = g_y + r0;
        for (int j = tid; j < 32 * 256; j += 256) {
            int t = j >> 8, col = j & 255;
            cpa4(smem_u32(ss + t * 256 + col), src + (size_t)t * SROWS + col);
        }
        cpa_commit();
    }

    float nu1[31];
    #pragma unroll
    for (int d = 1; d <= 31; d++) {
        float td = (float)d;
        nu1[d - 1] = (-20.0f * td) * expf(1.0f - td);
    }
    float rf[32];
    #pragma unroll
    for (int i = 0; i < 32; i++) rf[i] = 0.0f;

    for (int tile = 0; tile < 11; tile++) {
        const int tl = (tile == 10) ? 5 : 32;
        if (tile < 10) {
            const int nt = (tile == 9) ? 5 : 32;
            const float* src = g_y + (size_t)(tile + 1) * 32 * SROWS + r0;
            float* dst = ss + ((tile + 1) & 1) * (32 * 256);
            for (int j = tid; j < nt * 256; j += 256) {
                int t = j >> 8, col = j & 255;
                cpa4(smem_u32(dst + t * 256 + col), src + (size_t)t * SROWS + col);
            }
            cpa_commit();
            asm volatile("cp.async.wait_group 1;");
        } else {
            asm volatile("cp.async.wait_group 0;");
        }
        __syncthreads();

        const float* yb = ss + (tile & 1) * (32 * 256);
        #pragma unroll 8
        for (int t = 0; t < tl; t++) {
            float v = yb[t * 256 + tid] + rf[0];
            float s = (v >= 10.0f) ? 1.0f : 0.0f;
            sbuf[tid * 33 + t] = s;
            #pragma unroll
            for (int i = 0; i < 31; i++) rf[i] = fmaf(s, nu1[i], rf[i + 1]);
            rf[31] = 0.0f;
        }
        __syncthreads();

        const int tbase = tile * 32;
        const int lane = tid & 31;
        for (int base = 0; base < 256; base += 8) {
            int row = base + (tid >> 5);
            if (lane < tl)
                out[(size_t)(r0 + row) * TT + tbase + lane] = sbuf[row * 33 + lane];
        }
        // loop-top __syncthreads orders flush-reads before next scan-writes
    }
}

extern "C" void kernel_launch(void* const* d_in, const int* in_sizes, int n_in,
                              void* d_out, int out_size)
{
    const float* x = (const float*)d_in[0];
    const float* w = (const float*)d_in[1];
    if (n_in >= 2 && in_sizes[0] == COUT * CIN) {
        x = (const float*)d_in[1];
        w = (const float*)d_in[0];
    }
    cudaFuncSetAttribute(convgemm_kernel, cudaFuncAttributeMaxDynamicSharedMemorySize,
                         SMEM_FLOATS * (int)sizeof(float));
    cudaFuncSetAttribute(scan_kernel, cudaFuncAttributeMaxDynamicSharedMemorySize,
                         SC_SMEM);
    convgemm_kernel<<<NB * 2, THREADS, SMEM_FLOATS * sizeof(float)>>>(x, w);
    scan_kernel<<<SROWS / 256, 256, SC_SMEM>>>((float*)d_out);
}